// round 4
// baseline (speedup 1.0000x reference)
#include <cuda_runtime.h>
#include <math.h>

#define T_STEPS 256
#define B_SZ    1024
#define Y_DIM   32
#define H_DIM   1024
#define R_DIM   512
#define R3      (3 * R_DIM)

// ---------------- scratch (device globals: no allocation allowed) ----------------
__device__ float  g_h0[B_SZ * R_DIM];
__device__ float  g_h1[B_SZ * R_DIM];
__device__ float  g_d1[B_SZ * H_DIM];
__device__ float  g_d2[B_SZ * H_DIM];
__device__ float  g_GI[B_SZ * R3];
__device__ float  g_GH[B_SZ * R3];
__device__ double g_nll;
__device__ unsigned int g_bar;   // zero-initialized; reset by finalize kernel each run

struct Smem {
    float As[16][64];
    float Ws[16][64];
    float Cs[64][65];
    float wsum[8];
};

// ---------------- grid-wide barrier (all blocks resident by construction) ----------------
__device__ __forceinline__ void grid_sync(unsigned int target) {
    __threadfence();          // release: make this thread's writes visible device-wide
    __syncthreads();          // order all block threads' fences before the arrive
    if (threadIdx.x == 0) {
        atomicAdd(&g_bar, 1u);
        while (*((volatile unsigned int*)&g_bar) < target) { __nanosleep(64); }
        __threadfence();      // acquire
    }
    __syncthreads();
}

// ---------------- 64x64 GEMM tile: C[bm:+64, bn:+64] = act(A@W^T + bias) ----------------
// A row-major [M,K], W row-major [N,K], C row-major [M,N]. K multiple of 16.
__device__ __forceinline__ void gemm_tile(float* __restrict__ C,
                                          const float* __restrict__ A,
                                          const float* __restrict__ W,
                                          const float* __restrict__ bias,
                                          int N, int K, int bm, int bn, int act,
                                          Smem* sm) {
    const int tid = threadIdx.x;
    const int tx = tid & 15, ty = tid >> 4;
    const int lr = tid >> 2;            // 0..63
    const int lk = (tid & 3) << 2;      // 0,4,8,12

    const float* Ap = A + (size_t)(bm + lr) * K + lk;
    const float* Wp = W + (size_t)(bn + lr) * K + lk;

    float acc[4][4];
#pragma unroll
    for (int i = 0; i < 4; i++)
#pragma unroll
        for (int j = 0; j < 4; j++) acc[i][j] = 0.0f;

    for (int k0 = 0; k0 < K; k0 += 16) {
        float4 av = *(const float4*)(Ap + k0);
        float4 wv = *(const float4*)(Wp + k0);
        sm->As[lk + 0][lr] = av.x; sm->As[lk + 1][lr] = av.y;
        sm->As[lk + 2][lr] = av.z; sm->As[lk + 3][lr] = av.w;
        sm->Ws[lk + 0][lr] = wv.x; sm->Ws[lk + 1][lr] = wv.y;
        sm->Ws[lk + 2][lr] = wv.z; sm->Ws[lk + 3][lr] = wv.w;
        __syncthreads();
#pragma unroll
        for (int k = 0; k < 16; k++) {
            float4 a = *(const float4*)&sm->As[k][ty << 2];
            float4 b = *(const float4*)&sm->Ws[k][tx << 2];
            float ar[4] = {a.x, a.y, a.z, a.w};
            float br[4] = {b.x, b.y, b.z, b.w};
#pragma unroll
            for (int i = 0; i < 4; i++)
#pragma unroll
                for (int j = 0; j < 4; j++) acc[i][j] += ar[i] * br[j];
        }
        __syncthreads();
    }

    float4 bv = *(const float4*)&bias[bn + (tx << 2)];
    float bj[4] = {bv.x, bv.y, bv.z, bv.w};
#pragma unroll
    for (int i = 0; i < 4; i++) {
        float4 o;
        o.x = acc[i][0] + bj[0];
        o.y = acc[i][1] + bj[1];
        o.z = acc[i][2] + bj[2];
        o.w = acc[i][3] + bj[3];
        if (act) {
            o.x = fmaxf(o.x, 0.0f); o.y = fmaxf(o.y, 0.0f);
            o.z = fmaxf(o.z, 0.0f); o.w = fmaxf(o.w, 0.0f);
        }
        *(float4*)(C + (size_t)(bm + (ty << 2) + i) * N + bn + (tx << 2)) = o;
    }
}

// ---------------- fused heads + NLL for 64 batch rows ----------------
__device__ __forceinline__ void heads_tile(int bm,
                                           const float* __restrict__ D,
                                           const float* __restrict__ mw,
                                           const float* __restrict__ mb,
                                           const float* __restrict__ sw,
                                           const float* __restrict__ sb,
                                           const float* __restrict__ yt,
                                           Smem* sm) {
    const int tid = threadIdx.x;
    const int tx = tid & 15, ty = tid >> 4;
    const int lr = tid >> 2;
    const int lk = (tid & 3) << 2;
    const int K = H_DIM;

    const float* Ap = D + (size_t)(bm + lr) * K + lk;
    const float* Wrow = (lr < 32) ? (mw + (size_t)lr * K) : (sw + (size_t)(lr - 32) * K);

    float acc[4][4];
#pragma unroll
    for (int i = 0; i < 4; i++)
#pragma unroll
        for (int j = 0; j < 4; j++) acc[i][j] = 0.0f;

    for (int k0 = 0; k0 < K; k0 += 16) {
        float4 av = *(const float4*)(Ap + k0);
        float4 wv = *(const float4*)(Wrow + lk + k0);
        sm->As[lk + 0][lr] = av.x; sm->As[lk + 1][lr] = av.y;
        sm->As[lk + 2][lr] = av.z; sm->As[lk + 3][lr] = av.w;
        sm->Ws[lk + 0][lr] = wv.x; sm->Ws[lk + 1][lr] = wv.y;
        sm->Ws[lk + 2][lr] = wv.z; sm->Ws[lk + 3][lr] = wv.w;
        __syncthreads();
#pragma unroll
        for (int k = 0; k < 16; k++) {
            float4 a = *(const float4*)&sm->As[k][ty << 2];
            float4 b = *(const float4*)&sm->Ws[k][tx << 2];
            float ar[4] = {a.x, a.y, a.z, a.w};
            float br[4] = {b.x, b.y, b.z, b.w};
#pragma unroll
            for (int i = 0; i < 4; i++)
#pragma unroll
                for (int j = 0; j < 4; j++) acc[i][j] += ar[i] * br[j];
        }
        __syncthreads();
    }

#pragma unroll
    for (int i = 0; i < 4; i++)
#pragma unroll
        for (int j = 0; j < 4; j++) {
            int c = (tx << 2) + j;
            float bb = (c < 32) ? mb[c] : sb[c - 32];
            sm->Cs[(ty << 2) + i][c] = acc[i][j] + bb;
        }
    __syncthreads();

    const float LOG2PI = 1.8378770664093453f;
    float local = 0.0f;
    for (int idx = tid; idx < 64 * 32; idx += 256) {
        int b = idx >> 5, yc = idx & 31;
        float mean = sm->Cs[b][yc];
        float s = sm->Cs[b][yc + 32];
        float std = (s > 15.0f) ? s : log1pf(expf(s));
        float diff = yt[(size_t)(bm + b) * Y_DIM + yc] - mean;
        local += diff * diff / (std * std) + 2.0f * logf(std) + LOG2PI;
    }
#pragma unroll
    for (int o = 16; o > 0; o >>= 1) local += __shfl_xor_sync(0xffffffffu, local, o);
    if ((tid & 31) == 0) sm->wsum[tid >> 5] = local;
    __syncthreads();
    if (tid == 0) {
        float s = 0.0f;
#pragma unroll
        for (int w = 0; w < 8; w++) s += sm->wsum[w];
        atomicAdd(&g_nll, (double)(0.5f * s));
    }
    __syncthreads();
}

// ---------------- GRU gate chunk: 256 consecutive elements of h ----------------
__device__ __forceinline__ void gates_chunk(float* __restrict__ h, int chunk) {
    int i = chunk * 256 + threadIdx.x;
    int b = i >> 9;                 // / R_DIM
    int n = i & (R_DIM - 1);
    size_t base = (size_t)b * R3 + n;
    float gir = g_GI[base], giz = g_GI[base + R_DIM], gin = g_GI[base + 2 * R_DIM];
    float ghr = g_GH[base], ghz = g_GH[base + R_DIM], ghn = g_GH[base + 2 * R_DIM];
    float r = 1.0f / (1.0f + expf(-(gir + ghr)));
    float z = 1.0f / (1.0f + expf(-(giz + ghz)));
    float nn = tanhf(gin + r * ghn);
    h[i] = (1.0f - z) * nn + z * h[i];
}

// ---------------- the whole model as one persistent kernel ----------------
__global__ __launch_bounds__(256) void rnn_persistent(
    const float* __restrict__ y,
    const float* __restrict__ dec_w1, const float* __restrict__ dec_b1,
    const float* __restrict__ dec_w2, const float* __restrict__ dec_b2,
    const float* __restrict__ mean_w, const float* __restrict__ mean_b,
    const float* __restrict__ std_w,  const float* __restrict__ std_b,
    const float* __restrict__ wih0,   const float* __restrict__ whh0,
    const float* __restrict__ bih0,   const float* __restrict__ bhh0,
    const float* __restrict__ wih1,   const float* __restrict__ whh1,
    const float* __restrict__ bih1,   const float* __restrict__ bhh1) {
    __shared__ Smem sm;
    const int nb = gridDim.x;
    unsigned int gen = 0;

    // init h0, h1, nll
    for (int i = blockIdx.x * 256 + threadIdx.x; i < B_SZ * R_DIM; i += nb * 256) {
        g_h0[i] = 0.0f; g_h1[i] = 0.0f;
    }
    if (blockIdx.x == 0 && threadIdx.x == 0) g_nll = 0.0;
    gen++; grid_sync(gen * nb);

    for (int t = 0; t < T_STEPS; t++) {
        const float* yt = y + (size_t)t * B_SZ * Y_DIM;

        // Phase A: dec1 (256) | GI0 (384) | GH0 (384)
        for (int w = blockIdx.x; w < 1024; w += nb) {
            if (w < 256) {
                gemm_tile(g_d1, g_h1, dec_w1, dec_b1, H_DIM, R_DIM,
                          (w >> 4) << 6, (w & 15) << 6, 1, &sm);
            } else if (w < 640) {
                int u = w - 256;
                gemm_tile(g_GI, yt, wih0, bih0, R3, Y_DIM,
                          (u / 24) << 6, (u % 24) << 6, 0, &sm);
            } else {
                int u = w - 640;
                gemm_tile(g_GH, g_h0, whh0, bhh0, R3, R_DIM,
                          (u / 24) << 6, (u % 24) << 6, 0, &sm);
            }
        }
        gen++; grid_sync(gen * nb);

        // Phase B: dec2 (256 tiles) | gates0 (2048 chunks -> h0)
        for (int w = blockIdx.x; w < 256 + 2048; w += nb) {
            if (w < 256) {
                gemm_tile(g_d2, g_d1, dec_w2, dec_b2, H_DIM, H_DIM,
                          (w >> 4) << 6, (w & 15) << 6, 1, &sm);
            } else {
                gates_chunk(g_h0, w - 256);
            }
        }
        gen++; grid_sync(gen * nb);

        // Phase C: heads+NLL (16) | GI1 (384) | GH1 (384)
        for (int w = blockIdx.x; w < 784; w += nb) {
            if (w < 16) {
                heads_tile(w << 6, g_d2, mean_w, mean_b, std_w, std_b, yt, &sm);
            } else if (w < 400) {
                int u = w - 16;
                gemm_tile(g_GI, g_h0, wih1, bih1, R3, R_DIM,
                          (u / 24) << 6, (u % 24) << 6, 0, &sm);
            } else {
                int u = w - 400;
                gemm_tile(g_GH, g_h1, whh1, bhh1, R3, R_DIM,
                          (u / 24) << 6, (u % 24) << 6, 0, &sm);
            }
        }
        gen++; grid_sync(gen * nb);

        // Phase D: gates1 (2048 chunks -> h1)
        for (int w = blockIdx.x; w < 2048; w += nb) gates_chunk(g_h1, w);
        if (t != T_STEPS - 1) { gen++; grid_sync(gen * nb); }
        // last step: kernel exit is the barrier
    }
}

// finalize in a separate launch: reads g_nll after the persistent kernel fully
// drains, and resets the barrier counter for the next replay (doing the reset
// inside the main kernel races with blocks still spinning on the last barrier).
__global__ void finalize_kernel(float* out) {
    out[0] = (float)g_nll;
    g_bar = 0u;
}

extern "C" void kernel_launch(void* const* d_in, const int* in_sizes, int n_in,
                              void* d_out, int out_size) {
    const float* y      = (const float*)d_in[0];
    const float* dec_w1 = (const float*)d_in[1];
    const float* dec_b1 = (const float*)d_in[2];
    const float* dec_w2 = (const float*)d_in[3];
    const float* dec_b2 = (const float*)d_in[4];
    const float* mean_w = (const float*)d_in[5];
    const float* mean_b = (const float*)d_in[6];
    const float* std_w  = (const float*)d_in[7];
    const float* std_b  = (const float*)d_in[8];
    const float* wih0   = (const float*)d_in[9];
    const float* whh0   = (const float*)d_in[10];
    const float* bih0   = (const float*)d_in[11];
    const float* bhh0   = (const float*)d_in[12];
    const float* wih1   = (const float*)d_in[13];
    const float* whh1   = (const float*)d_in[14];
    const float* bih1   = (const float*)d_in[15];
    const float* bhh1   = (const float*)d_in[16];

    // size the grid so every block is resident (required for the grid barrier)
    int dev = 0, nsm = 0, bpm = 0;
    cudaGetDevice(&dev);
    cudaDeviceGetAttribute(&nsm, cudaDevAttrMultiProcessorCount, dev);
    cudaOccupancyMaxActiveBlocksPerMultiprocessor(&bpm, rnn_persistent, 256, 0);
    if (bpm < 1) bpm = 1;
    int grid = nsm * bpm;
    if (grid > 1024) grid = 1024;   // no benefit beyond max phase tile count

    rnn_persistent<<<grid, 256>>>(y, dec_w1, dec_b1, dec_w2, dec_b2,
                                  mean_w, mean_b, std_w, std_b,
                                  wih0, whh0, bih0, bhh0,
                                  wih1, whh1, bih1, bhh1);
    finalize_kernel<<<1, 1>>>((float*)d_out);
}

// round 6
// speedup vs baseline: 3.5130x; 3.5130x over previous
#include <cuda_runtime.h>
#include <cuda_fp16.h>
#include <cstdint>
#include <math.h>

#define T_STEPS 256
#define B_SZ    1024
#define Y_DIM   32
#define H_DIM   1024
#define R_DIM   512
#define R3      1536

__device__ float  g_h0[B_SZ * R_DIM];
__device__ float  g_h1[B_SZ * R_DIM];
__device__ float  g_d1[B_SZ * H_DIM];
__device__ float  g_d2[B_SZ * H_DIM];
__device__ float  g_GI[B_SZ * R3];
__device__ float  g_GH[B_SZ * R3];
__device__ double g_nll;
__device__ unsigned int g_bar;

// smem: A/B staging for mma unioned with heads C staging
struct SmemU {
    union {
        struct { uint32_t As[128][36]; uint32_t Bs[64][36]; } g;   // 27648 B
        float Cs[128 * 68];                                        // 34816 B
    } u;
    float red[8];
};

// ---------------- grid barrier ----------------
__device__ __forceinline__ void grid_sync(unsigned int target) {
    __threadfence();
    __syncthreads();
    if (threadIdx.x == 0) {
        atomicAdd(&g_bar, 1u);
        while (*((volatile unsigned int*)&g_bar) < target) { __nanosleep(64); }
        __threadfence();
    }
    __syncthreads();
}

// ---------------- warp mma ----------------
__device__ __forceinline__ void mma16816(float* c, uint32_t a0, uint32_t a1,
                                         uint32_t a2, uint32_t a3,
                                         uint32_t b0, uint32_t b1) {
    asm volatile("mma.sync.aligned.m16n8k16.row.col.f32.f16.f16.f32 "
                 "{%0,%1,%2,%3}, {%4,%5,%6,%7}, {%8,%9}, {%0,%1,%2,%3};"
                 : "+f"(c[0]), "+f"(c[1]), "+f"(c[2]), "+f"(c[3])
                 : "r"(a0), "r"(a1), "r"(a2), "r"(a3), "r"(b0), "r"(b1));
}

// ---------------- K-loop: acc[4][2][4] += A[bm:+128, :K] @ [W0|W1]^T (tile N=64) ----------------
// W0 rows [0, split), W1 rows [split, 64). Both row-major with row length K.
__device__ __forceinline__ void run_mma(SmemU* sm, const float* A, int ldA, int K,
                                        const float* W0, const float* W1, int split,
                                        int bm, float acc[4][2][4], int tid) {
    const int lane = tid & 31, w = tid >> 5;
    const int wm = (w >> 2) * 64, wn = (w & 3) * 16;
#pragma unroll
    for (int mt = 0; mt < 4; mt++)
#pragma unroll
        for (int nt = 0; nt < 2; nt++)
#pragma unroll
            for (int i = 0; i < 4; i++) acc[mt][nt][i] = 0.0f;

    for (int k0 = 0; k0 < K; k0 += 64) {
        const int kw = (K - k0 < 64) ? (K - k0) : 64;
        const int nq = kw >> 2;                 // float4s per row
        // stage A (128 x kw) as half2
        for (int idx = tid; idx < 128 * nq; idx += 256) {
            int r = idx / nq, q = idx - r * nq;
            float4 v = *(const float4*)(A + (size_t)(bm + r) * ldA + k0 + q * 4);
            __half2 h0 = __floats2half2_rn(v.x, v.y);
            __half2 h1 = __floats2half2_rn(v.z, v.w);
            sm->u.g.As[r][2 * q]     = *(uint32_t*)&h0;
            sm->u.g.As[r][2 * q + 1] = *(uint32_t*)&h1;
        }
        // stage B (64 x kw)
        for (int idx = tid; idx < 64 * nq; idx += 256) {
            int r = idx / nq, q = idx - r * nq;
            const float* Wr = (r < split) ? W0 + (size_t)r * K : W1 + (size_t)(r - split) * K;
            float4 v = *(const float4*)(Wr + k0 + q * 4);
            __half2 h0 = __floats2half2_rn(v.x, v.y);
            __half2 h1 = __floats2half2_rn(v.z, v.w);
            sm->u.g.Bs[r][2 * q]     = *(uint32_t*)&h0;
            sm->u.g.Bs[r][2 * q + 1] = *(uint32_t*)&h1;
        }
        __syncthreads();
        const int ksteps = kw >> 4;
        for (int s = 0; s < ksteps; s++) {
            const int kc = s * 8 + (lane & 3);
            const int bn0 = wn + (lane >> 2);
            uint32_t b00 = sm->u.g.Bs[bn0][kc],     b01 = sm->u.g.Bs[bn0][kc + 4];
            uint32_t b10 = sm->u.g.Bs[bn0 + 8][kc], b11 = sm->u.g.Bs[bn0 + 8][kc + 4];
#pragma unroll
            for (int mt = 0; mt < 4; mt++) {
                int r0 = wm + mt * 16 + (lane >> 2);
                uint32_t a0 = sm->u.g.As[r0][kc],     a1 = sm->u.g.As[r0 + 8][kc];
                uint32_t a2 = sm->u.g.As[r0][kc + 4], a3 = sm->u.g.As[r0 + 8][kc + 4];
                mma16816(acc[mt][0], a0, a1, a2, a3, b00, b01);
                mma16816(acc[mt][1], a0, a1, a2, a3, b10, b11);
            }
        }
        __syncthreads();
    }
}

// ---------------- plain tile: C[bm:+128, bn:+64] = act(A@W^T + bias) ----------------
__device__ void tile_gemm(SmemU* sm, const float* A, int ldA, int K,
                          const float* W, const float* bias, float* C, int ldC,
                          int bm, int bn, int relu, int tid) {
    float acc[4][2][4];
    const float* W0 = W + (size_t)bn * K;
    run_mma(sm, A, ldA, K, W0, W0, 64, bm, acc, tid);
    const int lane = tid & 31, w = tid >> 5;
    const int wm = (w >> 2) * 64, wn = (w & 3) * 16;
#pragma unroll
    for (int mt = 0; mt < 4; mt++)
#pragma unroll
        for (int nt = 0; nt < 2; nt++) {
            int row = bm + wm + mt * 16 + (lane >> 2);
            int col = bn + wn + nt * 8 + 2 * (lane & 3);
            float b0 = bias[col], b1 = bias[col + 1];
            float2 v;
            v.x = acc[mt][nt][0] + b0; v.y = acc[mt][nt][1] + b1;
            if (relu) { v.x = fmaxf(v.x, 0.f); v.y = fmaxf(v.y, 0.f); }
            *(float2*)(C + (size_t)row * ldC + col) = v;
            v.x = acc[mt][nt][2] + b0; v.y = acc[mt][nt][3] + b1;
            if (relu) { v.x = fmaxf(v.x, 0.f); v.y = fmaxf(v.y, 0.f); }
            *(float2*)(C + (size_t)(row + 8) * ldC + col) = v;
        }
}

// ---------------- heads tile: 128 rows x (mean 32 | std 32) + fused NLL ----------------
__device__ void tile_heads(SmemU* sm, int bm, const float* D,
                           const float* mw, const float* mb_,
                           const float* sw, const float* sb_,
                           const float* yt, int tid) {
    float acc[4][2][4];
    run_mma(sm, D, H_DIM, H_DIM, mw, sw, 32, bm, acc, tid);
    const int lane = tid & 31, w = tid >> 5;
    const int wm = (w >> 2) * 64, wn = (w & 3) * 16;
#pragma unroll
    for (int mt = 0; mt < 4; mt++)
#pragma unroll
        for (int nt = 0; nt < 2; nt++) {
            int row = wm + mt * 16 + (lane >> 2);
            int col = wn + nt * 8 + 2 * (lane & 3);
            float b0 = (col < 32) ? mb_[col] : sb_[col - 32];
            float b1 = (col + 1 < 32) ? mb_[col + 1] : sb_[col + 1 - 32];
            sm->u.Cs[row * 68 + col]           = acc[mt][nt][0] + b0;
            sm->u.Cs[row * 68 + col + 1]       = acc[mt][nt][1] + b1;
            sm->u.Cs[(row + 8) * 68 + col]     = acc[mt][nt][2] + b0;
            sm->u.Cs[(row + 8) * 68 + col + 1] = acc[mt][nt][3] + b1;
        }
    __syncthreads();
    const float LOG2PI = 1.8378770664093453f;
    float local = 0.0f;
    for (int idx = tid; idx < 128 * 32; idx += 256) {
        int b = idx >> 5, yc = idx & 31;
        float mean = sm->u.Cs[b * 68 + yc];
        float s = sm->u.Cs[b * 68 + 32 + yc];
        float std = (s > 15.0f) ? s : log1pf(expf(s));
        float diff = yt[(size_t)(bm + b) * Y_DIM + yc] - mean;
        local += diff * diff / (std * std) + 2.0f * logf(std) + LOG2PI;
    }
#pragma unroll
    for (int o = 16; o > 0; o >>= 1) local += __shfl_xor_sync(0xffffffffu, local, o);
    if ((tid & 31) == 0) sm->red[tid >> 5] = local;
    __syncthreads();
    if (tid == 0) {
        float s = 0.f;
#pragma unroll
        for (int i = 0; i < 8; i++) s += sm->red[i];
        atomicAdd(&g_nll, (double)(0.5f * s));
    }
    __syncthreads();
}

__device__ __forceinline__ void gates_chunk(float* __restrict__ h, int chunk) {
    int i = chunk * 256 + threadIdx.x;
    int b = i >> 9, n = i & (R_DIM - 1);
    size_t base = (size_t)b * R3 + n;
    float gir = g_GI[base], giz = g_GI[base + R_DIM], gin = g_GI[base + 2 * R_DIM];
    float ghr = g_GH[base], ghz = g_GH[base + R_DIM], ghn = g_GH[base + 2 * R_DIM];
    float r = 1.0f / (1.0f + expf(-(gir + ghr)));
    float z = 1.0f / (1.0f + expf(-(giz + ghz)));
    float nn = tanhf(gin + r * ghn);
    h[i] = (1.0f - z) * nn + z * h[i];
}

// ---------------- persistent kernel ----------------
__global__ __launch_bounds__(256) void rnn_mma(
    const float* __restrict__ y,
    const float* __restrict__ dec_w1, const float* __restrict__ dec_b1,
    const float* __restrict__ dec_w2, const float* __restrict__ dec_b2,
    const float* __restrict__ mean_w, const float* __restrict__ mean_b,
    const float* __restrict__ std_w,  const float* __restrict__ std_b,
    const float* __restrict__ wih0,   const float* __restrict__ whh0,
    const float* __restrict__ bih0,   const float* __restrict__ bhh0,
    const float* __restrict__ wih1,   const float* __restrict__ whh1,
    const float* __restrict__ bih1,   const float* __restrict__ bhh1) {
    __shared__ SmemU sm;
    const int tid = threadIdx.x, nb = gridDim.x;

    for (int i = blockIdx.x * 256 + tid; i < B_SZ * R_DIM; i += nb * 256) {
        g_h0[i] = 0.0f; g_h1[i] = 0.0f;
    }
    if (blockIdx.x == 0 && tid == 0) g_nll = 0.0;
    unsigned int gen = 1;
    grid_sync(gen * nb);

    for (int t = 0; t < T_STEPS; t++) {
        const float* yt = y + (size_t)t * B_SZ * Y_DIM;

        // Phase A: dec1 (128) | GI0 (192) | GH0 (192)
        for (int w = blockIdx.x; w < 512; w += nb) {
            if (w < 128) {
                tile_gemm(&sm, g_h1, R_DIM, R_DIM, dec_w1, dec_b1,
                          g_d1, H_DIM, (w >> 4) << 7, (w & 15) << 6, 1, tid);
            } else if (w < 320) {
                int u = w - 128;
                tile_gemm(&sm, yt, Y_DIM, Y_DIM, wih0, bih0,
                          g_GI, R3, (u / 24) << 7, (u % 24) << 6, 0, tid);
            } else {
                int u = w - 320;
                tile_gemm(&sm, g_h0, R_DIM, R_DIM, whh0, bhh0,
                          g_GH, R3, (u / 24) << 7, (u % 24) << 6, 0, tid);
            }
        }
        gen++; grid_sync(gen * nb);

        // Phase B: dec2 (128) | gates0 (2048)
        for (int w = blockIdx.x; w < 128 + 2048; w += nb) {
            if (w < 128) {
                tile_gemm(&sm, g_d1, H_DIM, H_DIM, dec_w2, dec_b2,
                          g_d2, H_DIM, (w >> 4) << 7, (w & 15) << 6, 1, tid);
            } else {
                gates_chunk(g_h0, w - 128);
            }
        }
        gen++; grid_sync(gen * nb);

        // Phase C: heads (8) | GI1 (192) | GH1 (192)
        for (int w = blockIdx.x; w < 392; w += nb) {
            if (w < 8) {
                tile_heads(&sm, w << 7, g_d2, mean_w, mean_b, std_w, std_b, yt, tid);
            } else if (w < 200) {
                int u = w - 8;
                tile_gemm(&sm, g_h0, R_DIM, R_DIM, wih1, bih1,
                          g_GI, R3, (u / 24) << 7, (u % 24) << 6, 0, tid);
            } else {
                int u = w - 200;
                tile_gemm(&sm, g_h1, R_DIM, R_DIM, whh1, bhh1,
                          g_GH, R3, (u / 24) << 7, (u % 24) << 6, 0, tid);
            }
        }
        gen++; grid_sync(gen * nb);

        // Phase D: gates1 (2048)
        for (int w = blockIdx.x; w < 2048; w += nb) gates_chunk(g_h1, w);
        if (t != T_STEPS - 1) { gen++; grid_sync(gen * nb); }
    }
}

__global__ void finalize_kernel(float* out) {
    out[0] = (float)g_nll;
    g_bar = 0u;
}

extern "C" void kernel_launch(void* const* d_in, const int* in_sizes, int n_in,
                              void* d_out, int out_size) {
    const float* y      = (const float*)d_in[0];
    const float* dec_w1 = (const float*)d_in[1];
    const float* dec_b1 = (const float*)d_in[2];
    const float* dec_w2 = (const float*)d_in[3];
    const float* dec_b2 = (const float*)d_in[4];
    const float* mean_w = (const float*)d_in[5];
    const float* mean_b = (const float*)d_in[6];
    const float* std_w  = (const float*)d_in[7];
    const float* std_b  = (const float*)d_in[8];
    const float* wih0   = (const float*)d_in[9];
    const float* whh0   = (const float*)d_in[10];
    const float* bih0   = (const float*)d_in[11];
    const float* bhh0   = (const float*)d_in[12];
    const float* wih1   = (const float*)d_in[13];
    const float* whh1   = (const float*)d_in[14];
    const float* bih1   = (const float*)d_in[15];
    const float* bhh1   = (const float*)d_in[16];

    int dev = 0, nsm = 0;
    cudaGetDevice(&dev);
    cudaDeviceGetAttribute(&nsm, cudaDevAttrMultiProcessorCount, dev);

    rnn_mma<<<nsm, 256>>>(y, dec_w1, dec_b1, dec_w2, dec_b2,
                          mean_w, mean_b, std_w, std_b,
                          wih0, whh0, bih0, bhh0,
                          wih1, whh1, bih1, bhh1);
    finalize_kernel<<<1, 1>>>((float*)d_out);
}

// round 7
// speedup vs baseline: 9.0335x; 2.5714x over previous
#include <cuda_runtime.h>
#include <cuda_fp16.h>
#include <cstdint>
#include <math.h>

#define T_STEPS 256
#define B_SZ    1024
#define Y_DIM   32
#define H_DIM   1024
#define R_DIM   512
#define R3      1536
#define YP      64      // y padded to K=64

// ---------------- device-global scratch ----------------
__device__ float  g_h0[B_SZ * R_DIM], g_h1[B_SZ * R_DIM];
__device__ float  g_GI[B_SZ * R3],   g_GH[B_SZ * R3];
__device__ double g_nll;
__device__ unsigned int g_bar;

__device__ __half g_h0h[B_SZ * R_DIM], g_h1h[B_SZ * R_DIM];
__device__ __half g_d1h[B_SZ * H_DIM], g_d2h[B_SZ * H_DIM];
__device__ __half g_yh[B_SZ * YP];

__device__ __half hw_d1[H_DIM * R_DIM];   // dec_w1
__device__ __half hw_d2[H_DIM * H_DIM];   // dec_w2
__device__ __half hw_hd[64 * H_DIM];      // [mean_w; std_w]
__device__ __half hw_i0[R3 * YP];         // wih0 zero-padded K=32->64
__device__ __half hw_g0[R3 * R_DIM];      // whh0
__device__ __half hw_i1[R3 * R_DIM];      // wih1
__device__ __half hw_g1[R3 * R_DIM];      // whh1

struct SmemU {
    union {
        struct { char A[2][16384]; char B[2][8192]; } st;   // double-buffered chunks
        float Cs[128 * 68];                                  // heads staging
    } u;
    float red[8];
};
#define SWZ(o) ((o) ^ (((o) >> 3) & 0x70))

// ---------------- helpers ----------------
__device__ __forceinline__ uint32_t smem_u32(const void* p) {
    uint32_t a;
    asm("{ .reg .u64 t; cvta.to.shared.u64 t, %1; cvt.u32.u64 %0, t; }" : "=r"(a) : "l"(p));
    return a;
}
__device__ __forceinline__ void cp16(uint32_t dst, const void* src) {
    asm volatile("cp.async.cg.shared.global [%0], [%1], 16;" :: "r"(dst), "l"(src));
}
__device__ __forceinline__ void ldsm4(uint32_t& r0, uint32_t& r1, uint32_t& r2,
                                      uint32_t& r3, uint32_t a) {
    asm volatile("ldmatrix.sync.aligned.m8n8.x4.shared.b16 {%0,%1,%2,%3}, [%4];"
                 : "=r"(r0), "=r"(r1), "=r"(r2), "=r"(r3) : "r"(a));
}
__device__ __forceinline__ void mma16816(float* c, uint32_t a0, uint32_t a1,
                                         uint32_t a2, uint32_t a3,
                                         uint32_t b0, uint32_t b1) {
    asm volatile("mma.sync.aligned.m16n8k16.row.col.f32.f16.f16.f32 "
                 "{%0,%1,%2,%3}, {%4,%5,%6,%7}, {%8,%9}, {%0,%1,%2,%3};"
                 : "+f"(c[0]), "+f"(c[1]), "+f"(c[2]), "+f"(c[3])
                 : "r"(a0), "r"(a1), "r"(a2), "r"(a3), "r"(b0), "r"(b1));
}
__device__ __forceinline__ void grid_sync(unsigned int target) {
    __threadfence();
    __syncthreads();
    if (threadIdx.x == 0) {
        atomicAdd(&g_bar, 1u);
        while (*((volatile unsigned int*)&g_bar) < target) { __nanosleep(64); }
        __threadfence();
    }
    __syncthreads();
}

// ---------------- chunk staging: A 128x64h, B 64x64h, SW128 rows of 128B ----------------
__device__ __forceinline__ void stage_chunk(uint32_t dA, uint32_t dB,
                                            const __half* Ah, int ldA, int bm,
                                            const __half* Wh, int ldW, int k0, int tid) {
#pragma unroll
    for (int i = 0; i < 4; i++) {
        int e = tid + i * 256, r = e >> 3, q = e & 7;
        cp16(dA + SWZ(r * 128 + q * 16), Ah + (size_t)(bm + r) * ldA + k0 + q * 8);
    }
#pragma unroll
    for (int i = 0; i < 2; i++) {
        int e = tid + i * 256, r = e >> 3, q = e & 7;
        cp16(dB + SWZ(r * 128 + q * 16), Wh + (size_t)r * ldW + k0 + q * 8);
    }
    asm volatile("cp.async.commit_group;");
}

// ---------------- K-loop: acc += A[bm:+128, :K] @ W[0:64, :K]^T ----------------
__device__ void run_mma(SmemU* sm, const __half* Ah, int ldA, int K,
                        const __half* Wh, int bm, float acc[4][2][4], int tid) {
    uint32_t sA[2] = { smem_u32(sm->u.st.A[0]), smem_u32(sm->u.st.A[1]) };
    uint32_t sB[2] = { smem_u32(sm->u.st.B[0]), smem_u32(sm->u.st.B[1]) };
    const int lane = tid & 31, w = tid >> 5;
    const int wm = (w >> 2) * 64, wn = (w & 3) * 16;
    const int arow = lane & 15, acol = (lane >> 4) * 16;
    const int brow = wn + (lane & 7) + ((lane & 16) ? 8 : 0);
    const int bcol = (lane & 8) ? 16 : 0;
#pragma unroll
    for (int mt = 0; mt < 4; mt++)
#pragma unroll
        for (int nt = 0; nt < 2; nt++)
#pragma unroll
            for (int i = 0; i < 4; i++) acc[mt][nt][i] = 0.f;

    const int nch = K >> 6;
    stage_chunk(sA[0], sB[0], Ah, ldA, bm, Wh, K, 0, tid);
    for (int kc = 0; kc < nch; kc++) {
        if (kc + 1 < nch) {
            stage_chunk(sA[(kc + 1) & 1], sB[(kc + 1) & 1], Ah, ldA, bm, Wh, K,
                        (kc + 1) << 6, tid);
            asm volatile("cp.async.wait_group 1;");
        } else {
            asm volatile("cp.async.wait_group 0;");
        }
        __syncthreads();
        uint32_t aB = sA[kc & 1], bB = sB[kc & 1];
#pragma unroll
        for (int s = 0; s < 4; s++) {
            uint32_t b0, b1, b2, b3;
            ldsm4(b0, b1, b2, b3, bB + SWZ(brow * 128 + s * 32 + bcol));
#pragma unroll
            for (int mt = 0; mt < 4; mt++) {
                uint32_t a0, a1, a2, a3;
                ldsm4(a0, a1, a2, a3,
                      aB + SWZ((wm + mt * 16 + arow) * 128 + s * 32 + acol));
                mma16816(acc[mt][0], a0, a1, a2, a3, b0, b1);
                mma16816(acc[mt][1], a0, a1, a2, a3, b2, b3);
            }
        }
        __syncthreads();
    }
}

// ---------------- tile: C[bm:+128, bn:+64]; mode 0 = float out, 1 = half out + relu ----------------
__device__ void tile_gemm(SmemU* sm, const __half* Ah, int ldA, int K,
                          const __half* Wbase, const float* bias,
                          float* Cf, __half* Ch, int ldC,
                          int bm, int bn, int mode, int tid) {
    float acc[4][2][4];
    run_mma(sm, Ah, ldA, K, Wbase + (size_t)bn * K, bm, acc, tid);
    const int lane = tid & 31, w = tid >> 5;
    const int wm = (w >> 2) * 64, wn = (w & 3) * 16;
#pragma unroll
    for (int mt = 0; mt < 4; mt++)
#pragma unroll
        for (int nt = 0; nt < 2; nt++) {
            int row = bm + wm + mt * 16 + (lane >> 2);
            int col = bn + wn + nt * 8 + 2 * (lane & 3);
            float b0 = bias[col], b1 = bias[col + 1];
            float x0 = acc[mt][nt][0] + b0, x1 = acc[mt][nt][1] + b1;
            float x2 = acc[mt][nt][2] + b0, x3 = acc[mt][nt][3] + b1;
            if (mode == 1) {
                x0 = fmaxf(x0, 0.f); x1 = fmaxf(x1, 0.f);
                x2 = fmaxf(x2, 0.f); x3 = fmaxf(x3, 0.f);
                *(__half2*)(Ch + (size_t)row * ldC + col)       = __floats2half2_rn(x0, x1);
                *(__half2*)(Ch + (size_t)(row + 8) * ldC + col) = __floats2half2_rn(x2, x3);
            } else {
                *(float2*)(Cf + (size_t)row * ldC + col)       = make_float2(x0, x1);
                *(float2*)(Cf + (size_t)(row + 8) * ldC + col) = make_float2(x2, x3);
            }
        }
}

// ---------------- heads tile + fused NLL ----------------
__device__ void tile_heads(SmemU* sm, int bm, const float* mb_, const float* sb_,
                           const float* yt, int tid) {
    float acc[4][2][4];
    run_mma(sm, g_d2h, H_DIM, H_DIM, hw_hd, bm, acc, tid);
    const int lane = tid & 31, w = tid >> 5;
    const int wm = (w >> 2) * 64, wn = (w & 3) * 16;
#pragma unroll
    for (int mt = 0; mt < 4; mt++)
#pragma unroll
        for (int nt = 0; nt < 2; nt++) {
            int row = wm + mt * 16 + (lane >> 2);
            int col = wn + nt * 8 + 2 * (lane & 3);
            float b0 = (col < 32) ? mb_[col] : sb_[col - 32];
            float b1 = (col + 1 < 32) ? mb_[col + 1] : sb_[col + 1 - 32];
            sm->u.Cs[row * 68 + col]             = acc[mt][nt][0] + b0;
            sm->u.Cs[row * 68 + col + 1]         = acc[mt][nt][1] + b1;
            sm->u.Cs[(row + 8) * 68 + col]       = acc[mt][nt][2] + b0;
            sm->u.Cs[(row + 8) * 68 + col + 1]   = acc[mt][nt][3] + b1;
        }
    __syncthreads();
    const float LOG2PI = 1.8378770664093453f;
    float local = 0.0f;
    for (int idx = tid; idx < 128 * 32; idx += 256) {
        int b = idx >> 5, yc = idx & 31;
        float mean = sm->u.Cs[b * 68 + yc];
        float s = sm->u.Cs[b * 68 + 32 + yc];
        float std = (s > 15.0f) ? s : log1pf(expf(s));
        float diff = yt[(size_t)(bm + b) * Y_DIM + yc] - mean;
        local += diff * diff / (std * std) + 2.0f * logf(std) + LOG2PI;
    }
#pragma unroll
    for (int o = 16; o > 0; o >>= 1) local += __shfl_xor_sync(0xffffffffu, local, o);
    if ((tid & 31) == 0) sm->red[tid >> 5] = local;
    __syncthreads();
    if (tid == 0) {
        float s = 0.f;
#pragma unroll
        for (int i = 0; i < 8; i++) s += sm->red[i];
        atomicAdd(&g_nll, (double)(0.5f * s));
    }
    __syncthreads();
}

__device__ __forceinline__ void gates_chunk(float* __restrict__ h,
                                            __half* __restrict__ hh, int chunk, int tid) {
    int i = chunk * 256 + tid;
    int b = i >> 9, n = i & (R_DIM - 1);
    size_t base = (size_t)b * R3 + n;
    float gir = g_GI[base], giz = g_GI[base + R_DIM], gin = g_GI[base + 2 * R_DIM];
    float ghr = g_GH[base], ghz = g_GH[base + R_DIM], ghn = g_GH[base + 2 * R_DIM];
    float r = 1.0f / (1.0f + expf(-(gir + ghr)));
    float z = 1.0f / (1.0f + expf(-(giz + ghz)));
    float nn = tanhf(gin + r * ghn);
    float out = (1.0f - z) * nn + z * h[i];
    h[i] = out;
    hh[i] = __float2half(out);
}

// ---------------- persistent kernel ----------------
__global__ __launch_bounds__(256) void rnn_mma(
    const float* __restrict__ y,
    const float* __restrict__ dec_w1, const float* __restrict__ dec_b1,
    const float* __restrict__ dec_w2, const float* __restrict__ dec_b2,
    const float* __restrict__ mean_w, const float* __restrict__ mean_b,
    const float* __restrict__ std_w,  const float* __restrict__ std_b,
    const float* __restrict__ wih0,   const float* __restrict__ whh0,
    const float* __restrict__ bih0,   const float* __restrict__ bhh0,
    const float* __restrict__ wih1,   const float* __restrict__ whh1,
    const float* __restrict__ bih1,   const float* __restrict__ bhh1) {
    extern __shared__ char dynraw[];
    SmemU* sm = (SmemU*)dynraw;
    const int tid = threadIdx.x, nb = gridDim.x;
    const int gs = nb * 256, gi = blockIdx.x * 256 + tid;

    // ---- one-time conversions (amortized over 256 steps) ----
    for (int i = gi; i < H_DIM * R_DIM; i += gs) hw_d1[i] = __float2half(dec_w1[i]);
    for (int i = gi; i < H_DIM * H_DIM; i += gs) hw_d2[i] = __float2half(dec_w2[i]);
    for (int i = gi; i < 64 * H_DIM; i += gs) {
        int r = i >> 10, c = i & 1023;
        hw_hd[i] = __float2half(r < 32 ? mean_w[r * H_DIM + c] : std_w[(r - 32) * H_DIM + c]);
    }
    for (int i = gi; i < R3 * YP; i += gs) {
        int r = i >> 6, c = i & 63;
        hw_i0[i] = (c < 32) ? __float2half(wih0[r * Y_DIM + c]) : __float2half(0.f);
    }
    for (int i = gi; i < R3 * R_DIM; i += gs) {
        hw_g0[i] = __float2half(whh0[i]);
        hw_i1[i] = __float2half(wih1[i]);
        hw_g1[i] = __float2half(whh1[i]);
    }
    for (int i = gi; i < B_SZ * R_DIM; i += gs) {
        g_h0[i] = 0.f; g_h1[i] = 0.f;
        g_h0h[i] = __float2half(0.f); g_h1h[i] = __float2half(0.f);
    }
    for (int i = gi; i < B_SZ * YP; i += gs) {
        int b = i >> 6, c = i & 63;
        g_yh[i] = (c < 32) ? __float2half(y[(size_t)b * Y_DIM + c]) : __float2half(0.f);
    }
    if (blockIdx.x == 0 && tid == 0) g_nll = 0.0;
    unsigned int gen = 1;
    grid_sync(gen * nb);

    for (int t = 0; t < T_STEPS; t++) {
        const float* yt = y + (size_t)t * B_SZ * Y_DIM;

        // Phase A: dec1 (128) | GI0 (192) | GH0 (192)
        for (int w = blockIdx.x; w < 512; w += nb) {
            if (w < 128) {
                tile_gemm(sm, g_h1h, R_DIM, R_DIM, hw_d1, dec_b1,
                          nullptr, g_d1h, H_DIM, (w >> 4) << 7, (w & 15) << 6, 1, tid);
            } else if (w < 320) {
                int u = w - 128;
                tile_gemm(sm, g_yh, YP, YP, hw_i0, bih0,
                          g_GI, nullptr, R3, (u / 24) << 7, (u % 24) << 6, 0, tid);
            } else {
                int u = w - 320;
                tile_gemm(sm, g_h0h, R_DIM, R_DIM, hw_g0, bhh0,
                          g_GH, nullptr, R3, (u / 24) << 7, (u % 24) << 6, 0, tid);
            }
        }
        gen++; grid_sync(gen * nb);

        // Phase B: dec2 (128) | gates0 (2048)
        for (int w = blockIdx.x; w < 128 + 2048; w += nb) {
            if (w < 128) {
                tile_gemm(sm, g_d1h, H_DIM, H_DIM, hw_d2, dec_b2,
                          nullptr, g_d2h, H_DIM, (w >> 4) << 7, (w & 15) << 6, 1, tid);
            } else {
                gates_chunk(g_h0, g_h0h, w - 128, tid);
            }
        }
        gen++; grid_sync(gen * nb);

        // Phase C: heads (8) | GI1 (192) | GH1 (192)
        for (int w = blockIdx.x; w < 392; w += nb) {
            if (w < 8) {
                tile_heads(sm, w << 7, mean_b, std_b, yt, tid);
            } else if (w < 200) {
                int u = w - 8;
                tile_gemm(sm, g_h0h, R_DIM, R_DIM, hw_i1, bih1,
                          g_GI, nullptr, R3, (u / 24) << 7, (u % 24) << 6, 0, tid);
            } else {
                int u = w - 200;
                tile_gemm(sm, g_h1h, R_DIM, R_DIM, hw_g1, bhh1,
                          g_GH, nullptr, R3, (u / 24) << 7, (u % 24) << 6, 0, tid);
            }
        }
        gen++; grid_sync(gen * nb);

        // Phase D: gates1 (2048) | y conversion for next step (128)
        int extra = (t + 1 < T_STEPS) ? 128 : 0;
        for (int w = blockIdx.x; w < 2048 + extra; w += nb) {
            if (w < 2048) {
                gates_chunk(g_h1, g_h1h, w, tid);
            } else {
                int i = (w - 2048) * 256 + tid;
                int b = i >> 5, c = i & 31;
                g_yh[b * YP + c] = __float2half(y[(size_t)(t + 1) * B_SZ * Y_DIM + i]);
            }
        }
        if (t != T_STEPS - 1) { gen++; grid_sync(gen * nb); }
    }
}

__global__ void finalize_kernel(float* out) {
    out[0] = (float)g_nll;
    g_bar = 0u;
}

extern "C" void kernel_launch(void* const* d_in, const int* in_sizes, int n_in,
                              void* d_out, int out_size) {
    const float* y      = (const float*)d_in[0];
    const float* dec_w1 = (const float*)d_in[1];
    const float* dec_b1 = (const float*)d_in[2];
    const float* dec_w2 = (const float*)d_in[3];
    const float* dec_b2 = (const float*)d_in[4];
    const float* mean_w = (const float*)d_in[5];
    const float* mean_b = (const float*)d_in[6];
    const float* std_w  = (const float*)d_in[7];
    const float* std_b  = (const float*)d_in[8];
    const float* wih0   = (const float*)d_in[9];
    const float* whh0   = (const float*)d_in[10];
    const float* bih0   = (const float*)d_in[11];
    const float* bhh0   = (const float*)d_in[12];
    const float* wih1   = (const float*)d_in[13];
    const float* whh1   = (const float*)d_in[14];
    const float* bih1   = (const float*)d_in[15];
    const float* bhh1   = (const float*)d_in[16];

    cudaFuncSetAttribute(rnn_mma, cudaFuncAttributeMaxDynamicSharedMemorySize,
                         (int)sizeof(SmemU));
    int dev = 0, nsm = 0, bpm = 0;
    cudaGetDevice(&dev);
    cudaDeviceGetAttribute(&nsm, cudaDevAttrMultiProcessorCount, dev);
    cudaOccupancyMaxActiveBlocksPerMultiprocessor(&bpm, rnn_mma, 256, sizeof(SmemU));
    if (bpm < 1) bpm = 1;
    if (bpm > 2) bpm = 2;

    rnn_mma<<<nsm * bpm, 256, sizeof(SmemU)>>>(y, dec_w1, dec_b1, dec_w2, dec_b2,
                                               mean_w, mean_b, std_w, std_b,
                                               wih0, whh0, bih0, bhh0,
                                               wih1, whh1, bih1, bhh1);
    finalize_kernel<<<1, 1>>>((float*)d_out);
}

// round 8
// speedup vs baseline: 9.9897x; 1.1059x over previous
#include <cuda_runtime.h>
#include <cuda_fp16.h>
#include <cstdint>
#include <math.h>

#define T_STEPS 256
#define B_SZ    1024
#define Y_DIM   32
#define H_DIM   1024
#define R_DIM   512
#define R3      1536
#define YP      64

// ---------------- device-global scratch ----------------
__device__ float  g_h0[B_SZ * R_DIM], g_h1[B_SZ * R_DIM];
__device__ __half g_h0h[B_SZ * R_DIM], g_h1h[B_SZ * R_DIM];
__device__ __half g_d1h[B_SZ * H_DIM], g_d2h[B_SZ * H_DIM];
__device__ float  g_GH0[B_SZ * R3], g_GH1[B_SZ * R3];
__device__ float  g_gp[2 * B_SZ * R3];          // GI1 K-split partials
__device__ float  g_dp[4 * B_SZ * H_DIM];       // dec2 K-split partials
__device__ float  g_hp[4 * B_SZ * 64];          // heads K-split partials
__device__ __half g_yh[T_STEPS * B_SZ * YP];    // y padded to K=64, all steps
__device__ __half g_GI0[(size_t)T_STEPS * B_SZ * R3];  // precomputed y@wih0^T+bih0
__device__ double g_nllb[2048];
__device__ unsigned int g_bar;

__device__ __half hw_d1[H_DIM * R_DIM];
__device__ __half hw_d2[H_DIM * H_DIM];
__device__ __half hw_hd[128 * H_DIM];     // [mean_w; std_w; zeros] padded to 128 rows
__device__ __half hw_i0[R3 * YP];
__device__ __half hw_g0[R3 * R_DIM];
__device__ __half hw_i1[R3 * R_DIM];
__device__ __half hw_g1[R3 * R_DIM];

struct SmemS { char A[2][16384]; char B[2][16384]; float red[8]; };
#define SWZ(o) ((o) ^ (((o) >> 3) & 0x70))

// epilogue modes
#define M_FBIAS 0
#define M_HRELU 1
#define M_HBIAS 2
#define M_FRAW  3
#define M_FRAW64 4

// ---------------- helpers ----------------
__device__ __forceinline__ uint32_t smem_u32(const void* p) {
    uint32_t a;
    asm("{ .reg .u64 t; cvta.to.shared.u64 t, %1; cvt.u32.u64 %0, t; }" : "=r"(a) : "l"(p));
    return a;
}
__device__ __forceinline__ void cp16(uint32_t dst, const void* src) {
    asm volatile("cp.async.cg.shared.global [%0], [%1], 16;" :: "r"(dst), "l"(src));
}
__device__ __forceinline__ void ldsm4(uint32_t& r0, uint32_t& r1, uint32_t& r2,
                                      uint32_t& r3, uint32_t a) {
    asm volatile("ldmatrix.sync.aligned.m8n8.x4.shared.b16 {%0,%1,%2,%3}, [%4];"
                 : "=r"(r0), "=r"(r1), "=r"(r2), "=r"(r3) : "r"(a));
}
__device__ __forceinline__ void mma16816(float* c, uint32_t a0, uint32_t a1,
                                         uint32_t a2, uint32_t a3,
                                         uint32_t b0, uint32_t b1) {
    asm volatile("mma.sync.aligned.m16n8k16.row.col.f32.f16.f16.f32 "
                 "{%0,%1,%2,%3}, {%4,%5,%6,%7}, {%8,%9}, {%0,%1,%2,%3};"
                 : "+f"(c[0]), "+f"(c[1]), "+f"(c[2]), "+f"(c[3])
                 : "r"(a0), "r"(a1), "r"(a2), "r"(a3), "r"(b0), "r"(b1));
}
__device__ __forceinline__ void grid_sync(unsigned int target) {
    __threadfence();
    __syncthreads();
    if (threadIdx.x == 0) {
        atomicAdd(&g_bar, 1u);
        while (*((volatile unsigned int*)&g_bar) < target) { __nanosleep(64); }
        __threadfence();
    }
    __syncthreads();
}

// ---------------- staging: A 128x64h + B 128x64h per chunk ----------------
__device__ __forceinline__ void stage_chunk(uint32_t dA, uint32_t dB,
                                            const __half* Ah, int ldA, int bm,
                                            const __half* Wh, int ldW, int k0, int tid) {
#pragma unroll
    for (int i = 0; i < 4; i++) {
        int e = tid + i * 256, r = e >> 3, q = e & 7;
        cp16(dA + SWZ(r * 128 + q * 16), Ah + (size_t)(bm + r) * ldA + k0 + q * 8);
        cp16(dB + SWZ(r * 128 + q * 16), Wh + (size_t)r * ldW + k0 + q * 8);
    }
    asm volatile("cp.async.commit_group;");
}

// ---------------- K-loop: acc[4][4][4] += A[bm:+128, kbase:+klen] @ W[0:128, same]^T ----------------
__device__ void run_mma(SmemS* sm, const __half* Ah, int ldA,
                        const __half* Wh, int ldW, int kbase, int klen,
                        int bm, float acc[4][4][4], int tid) {
    uint32_t sA[2] = { smem_u32(sm->A[0]), smem_u32(sm->A[1]) };
    uint32_t sB[2] = { smem_u32(sm->B[0]), smem_u32(sm->B[1]) };
    const int lane = tid & 31, w = tid >> 5;
    const int wm = (w >> 2) * 64, wn = (w & 3) * 32;
    const int arow = lane & 15, acol = (lane >> 4) * 16;
    const int brow = (lane & 7) + ((lane & 16) ? 8 : 0);
    const int bcol = (lane & 8) ? 16 : 0;
#pragma unroll
    for (int mt = 0; mt < 4; mt++)
#pragma unroll
        for (int nt = 0; nt < 4; nt++)
#pragma unroll
            for (int i = 0; i < 4; i++) acc[mt][nt][i] = 0.f;

    const int nch = klen >> 6;
    stage_chunk(sA[0], sB[0], Ah, ldA, bm, Wh, ldW, kbase, tid);
    for (int kc = 0; kc < nch; kc++) {
        if (kc + 1 < nch) {
            stage_chunk(sA[(kc + 1) & 1], sB[(kc + 1) & 1], Ah, ldA, bm, Wh, ldW,
                        kbase + ((kc + 1) << 6), tid);
            asm volatile("cp.async.wait_group 1;");
        } else {
            asm volatile("cp.async.wait_group 0;");
        }
        __syncthreads();
        uint32_t aB = sA[kc & 1], bB = sB[kc & 1];
#pragma unroll
        for (int s = 0; s < 4; s++) {
            uint32_t b00, b01, b02, b03, b10, b11, b12, b13;
            ldsm4(b00, b01, b02, b03, bB + SWZ((wn + brow) * 128 + s * 32 + bcol));
            ldsm4(b10, b11, b12, b13, bB + SWZ((wn + 16 + brow) * 128 + s * 32 + bcol));
#pragma unroll
            for (int mt = 0; mt < 4; mt++) {
                uint32_t a0, a1, a2, a3;
                ldsm4(a0, a1, a2, a3, aB + SWZ((wm + mt * 16 + arow) * 128 + s * 32 + acol));
                mma16816(acc[mt][0], a0, a1, a2, a3, b00, b01);
                mma16816(acc[mt][1], a0, a1, a2, a3, b02, b03);
                mma16816(acc[mt][2], a0, a1, a2, a3, b10, b11);
                mma16816(acc[mt][3], a0, a1, a2, a3, b12, b13);
            }
        }
        __syncthreads();
    }
}

// ---------------- epilogue ----------------
__device__ void tile_out(float acc[4][4][4], int mode, const float* bias,
                         float* Cf, __half* Ch, int ldC, int bm, int bn, int tid) {
    const int lane = tid & 31, w = tid >> 5;
    const int wm = (w >> 2) * 64, wn = (w & 3) * 32;
#pragma unroll
    for (int mt = 0; mt < 4; mt++)
#pragma unroll
        for (int nt = 0; nt < 4; nt++) {
            int row = bm + wm + mt * 16 + (lane >> 2);
            int lcol = wn + ((nt >> 1) << 4) + ((nt & 1) << 3) + 2 * (lane & 3);
            int col = bn + lcol;
            float x0 = acc[mt][nt][0], x1 = acc[mt][nt][1];
            float x2 = acc[mt][nt][2], x3 = acc[mt][nt][3];
            if (mode == M_FRAW) {
                *(float2*)(Cf + (size_t)row * ldC + col)       = make_float2(x0, x1);
                *(float2*)(Cf + (size_t)(row + 8) * ldC + col) = make_float2(x2, x3);
            } else if (mode == M_FRAW64) {
                if (lcol < 64) {
                    *(float2*)(Cf + (size_t)row * 64 + lcol)       = make_float2(x0, x1);
                    *(float2*)(Cf + (size_t)(row + 8) * 64 + lcol) = make_float2(x2, x3);
                }
            } else {
                float b0 = bias[col], b1 = bias[col + 1];
                x0 += b0; x1 += b1; x2 += b0; x3 += b1;
                if (mode == M_HRELU) {
                    x0 = fmaxf(x0, 0.f); x1 = fmaxf(x1, 0.f);
                    x2 = fmaxf(x2, 0.f); x3 = fmaxf(x3, 0.f);
                }
                if (mode == M_FBIAS) {
                    *(float2*)(Cf + (size_t)row * ldC + col)       = make_float2(x0, x1);
                    *(float2*)(Cf + (size_t)(row + 8) * ldC + col) = make_float2(x2, x3);
                } else {
                    *(__half2*)(Ch + (size_t)row * ldC + col)       = __floats2half2_rn(x0, x1);
                    *(__half2*)(Ch + (size_t)(row + 8) * ldC + col) = __floats2half2_rn(x2, x3);
                }
            }
        }
}

__device__ __forceinline__ void tile_gemm(SmemS* sm, const __half* Ah, int ldA,
                                          const __half* W, int ldW, int kbase, int klen,
                                          int bm, int bn, int mode, const float* bias,
                                          float* Cf, __half* Ch, int ldC, int tid) {
    float acc[4][4][4];
    run_mma(sm, Ah, ldA, W + (size_t)bn * ldW, ldW, kbase, klen, bm, acc, tid);
    tile_out(acc, mode, bias, Cf, Ch, ldC, bm, bn, tid);
}

// ---------------- elementwise pieces ----------------
__device__ __forceinline__ void gates0_chunk(int t, int c, int tid) {
    int i = c * 256 + tid;
    int b = i >> 9, n = i & 511;
    size_t gio = (size_t)t * (B_SZ * R3) + (size_t)b * R3 + n;
    float gir = __half2float(g_GI0[gio]);
    float giz = __half2float(g_GI0[gio + 512]);
    float gin = __half2float(g_GI0[gio + 1024]);
    size_t gho = (size_t)b * R3 + n;
    float ghr = g_GH0[gho], ghz = g_GH0[gho + 512], ghn = g_GH0[gho + 1024];
    float r = 1.0f / (1.0f + expf(-(gir + ghr)));
    float z = 1.0f / (1.0f + expf(-(giz + ghz)));
    float nn = tanhf(gin + r * ghn);
    float out = (1.0f - z) * nn + z * g_h0[i];
    g_h0[i] = out;
    g_h0h[i] = __float2half(out);
}
__device__ __forceinline__ void gates1_chunk(const float* bih1, int c, int tid) {
    int i = c * 256 + tid;
    int b = i >> 9, n = i & 511;
    size_t o = (size_t)b * R3 + n;
    float gir = g_gp[o] + g_gp[B_SZ * R3 + o] + bih1[n];
    float giz = g_gp[o + 512] + g_gp[B_SZ * R3 + o + 512] + bih1[n + 512];
    float gin = g_gp[o + 1024] + g_gp[B_SZ * R3 + o + 1024] + bih1[n + 1024];
    float ghr = g_GH1[o], ghz = g_GH1[o + 512], ghn = g_GH1[o + 1024];
    float r = 1.0f / (1.0f + expf(-(gir + ghr)));
    float z = 1.0f / (1.0f + expf(-(giz + ghz)));
    float nn = tanhf(gin + r * ghn);
    float out = (1.0f - z) * nn + z * g_h1[i];
    g_h1[i] = out;
    g_h1h[i] = __float2half(out);
}
__device__ __forceinline__ void finish_chunk(const float* dec_b2, int c, int tid) {
    int e = c * 256 + tid;
    int col = e & 1023;
    float s = g_dp[e] + g_dp[(1 << 20) + e] + g_dp[(2 << 20) + e] + g_dp[(3 << 20) + e]
            + dec_b2[col];
    g_d2h[e] = __float2half(fmaxf(s, 0.f));
}
__device__ __forceinline__ void nll_chunk(const float* y, const float* mean_b,
                                          const float* std_b, int tt, int c, int tid,
                                          float& nll_acc) {
    int e = c * 256 + tid;
    int b = e >> 5, yc = e & 31;
    int o = b * 64 + yc;
    float mean = g_hp[o] + g_hp[65536 + o] + g_hp[131072 + o] + g_hp[196608 + o]
               + mean_b[yc];
    int o2 = o + 32;
    float sv = g_hp[o2] + g_hp[65536 + o2] + g_hp[131072 + o2] + g_hp[196608 + o2]
             + std_b[yc];
    float std = (sv > 15.0f) ? sv : log1pf(expf(sv));
    float diff = y[(size_t)tt * (B_SZ * Y_DIM) + b * 32 + yc] - mean;
    const float LOG2PI = 1.8378770664093453f;
    nll_acc += 0.5f * (diff * diff / (std * std) + 2.0f * logf(std) + LOG2PI);
}

// ---------------- persistent kernel ----------------
__global__ __launch_bounds__(256, 2) void rnn_mma(
    const float* __restrict__ y,
    const float* __restrict__ dec_w1, const float* __restrict__ dec_b1,
    const float* __restrict__ dec_w2, const float* __restrict__ dec_b2,
    const float* __restrict__ mean_w, const float* __restrict__ mean_b,
    const float* __restrict__ std_w,  const float* __restrict__ std_b,
    const float* __restrict__ wih0,   const float* __restrict__ whh0,
    const float* __restrict__ bih0,   const float* __restrict__ bhh0,
    const float* __restrict__ wih1,   const float* __restrict__ whh1,
    const float* __restrict__ bih1,   const float* __restrict__ bhh1) {
    extern __shared__ char dynraw[];
    SmemS* sm = (SmemS*)dynraw;
    const int tid = threadIdx.x, bid = blockIdx.x, nb = gridDim.x;
    const int gs = nb * 256, gi = bid * 256 + tid;
    float nll_acc = 0.0f;

    // ---- one-time conversions ----
    for (int i = gi; i < H_DIM * R_DIM; i += gs) hw_d1[i] = __float2half(dec_w1[i]);
    for (int i = gi; i < H_DIM * H_DIM; i += gs) hw_d2[i] = __float2half(dec_w2[i]);
    for (int i = gi; i < 128 * H_DIM; i += gs) {
        int r = i >> 10, c = i & 1023;
        float v = (r < 32) ? mean_w[r * H_DIM + c] : (r < 64) ? std_w[(r - 32) * H_DIM + c] : 0.f;
        hw_hd[i] = __float2half(v);
    }
    for (int i = gi; i < R3 * YP; i += gs) {
        int r = i >> 6, c = i & 63;
        hw_i0[i] = (c < 32) ? __float2half(wih0[r * Y_DIM + c]) : __float2half(0.f);
    }
    for (int i = gi; i < R3 * R_DIM; i += gs) {
        hw_g0[i] = __float2half(whh0[i]);
        hw_i1[i] = __float2half(wih1[i]);
        hw_g1[i] = __float2half(whh1[i]);
    }
    for (int i = gi; i < B_SZ * R_DIM; i += gs) {
        g_h0[i] = 0.f; g_h1[i] = 0.f;
        g_h0h[i] = __float2half(0.f); g_h1h[i] = __float2half(0.f);
    }
    for (int i = gi; i < T_STEPS * B_SZ * YP; i += gs) {
        int c = i & 63, b = (i >> 6) & 1023, t = i >> 16;
        g_yh[i] = (c < 32) ? __float2half(y[(size_t)t * (B_SZ * Y_DIM) + b * 32 + c])
                           : __float2half(0.f);
    }
    unsigned int gen = 1;
    grid_sync(gen * nb);

    // ---- precompute GI0 for all steps: 256 t x (8 m x 12 n) tiles, K=64 ----
    for (int u = bid; u < T_STEPS * 96; u += nb) {
        int t = u / 96, v = u - t * 96;
        int m = v / 12, n = v - m * 12;
        tile_gemm(sm, g_yh + (size_t)t * (B_SZ * YP), YP, hw_i0, YP, 0, YP,
                  m << 7, n << 7, M_HBIAS, bih0,
                  nullptr, g_GI0 + (size_t)t * (B_SZ * R3), R3, tid);
    }
    gen++; grid_sync(gen * nb);

    for (int t = 0; t < T_STEPS; t++) {
        // Phase A: dec1(64) | GH0(96) | GH1(96) | nll for t-1 (128)
        int totA = 256 + ((t > 0) ? 128 : 0);
        for (int u = bid; u < totA; u += nb) {
            if (u < 64) {
                tile_gemm(sm, g_h1h, R_DIM, hw_d1, R_DIM, 0, R_DIM,
                          (u >> 3) << 7, (u & 7) << 7, M_HRELU, dec_b1,
                          nullptr, g_d1h, H_DIM, tid);
            } else if (u < 160) {
                int v = u - 64, m = v / 12, n = v - m * 12;
                tile_gemm(sm, g_h0h, R_DIM, hw_g0, R_DIM, 0, R_DIM,
                          m << 7, n << 7, M_FBIAS, bhh0, g_GH0, nullptr, R3, tid);
            } else if (u < 256) {
                int v = u - 160, m = v / 12, n = v - m * 12;
                tile_gemm(sm, g_h1h, R_DIM, hw_g1, R_DIM, 0, R_DIM,
                          m << 7, n << 7, M_FBIAS, bhh1, g_GH1, nullptr, R3, tid);
            } else {
                nll_chunk(y, mean_b, std_b, t - 1, u - 256, tid, nll_acc);
            }
        }
        gen++; grid_sync(gen * nb);

        // Phase B: dec2 K-split4 (256) | gates0 (2048)
        for (int u = bid; u < 2304; u += nb) {
            if (u < 256) {
                int v = u >> 2, kp = u & 3;
                tile_gemm(sm, g_d1h, H_DIM, hw_d2, H_DIM, kp << 8, 256,
                          (v >> 3) << 7, (v & 7) << 7, M_FRAW, nullptr,
                          g_dp + (kp << 20), nullptr, H_DIM, tid);
            } else {
                gates0_chunk(t, u - 256, tid);
            }
        }
        gen++; grid_sync(gen * nb);

        // Phase C: GI1 K-split2 (192) | finish-dec2 (4096)
        for (int u = bid; u < 192 + 4096; u += nb) {
            if (u < 192) {
                int v = u >> 1, kp = u & 1, m = v / 12, n = v - m * 12;
                tile_gemm(sm, g_h0h, R_DIM, hw_i1, R_DIM, kp << 8, 256,
                          m << 7, n << 7, M_FRAW, nullptr,
                          g_gp + kp * (B_SZ * R3), nullptr, R3, tid);
            } else {
                finish_chunk(dec_b2, u - 192, tid);
            }
        }
        gen++; grid_sync(gen * nb);

        // Phase D: heads K-split4 (32) | gates1 (2048)
        for (int u = bid; u < 32 + 2048; u += nb) {
            if (u < 32) {
                int m = u >> 2, kp = u & 3;
                tile_gemm(sm, g_d2h, H_DIM, hw_hd, H_DIM, kp << 8, 256,
                          m << 7, 0, M_FRAW64, nullptr,
                          g_hp + (kp << 16), nullptr, 64, tid);
            } else {
                gates1_chunk(bih1, u - 32, tid);
            }
        }
        gen++; grid_sync(gen * nb);
    }

    // final NLL for t = 255
    for (int u = bid; u < 128; u += nb) nll_chunk(y, mean_b, std_b, 255, u, tid, nll_acc);

    // block-level reduction into g_nllb[bid]
#pragma unroll
    for (int o = 16; o > 0; o >>= 1) nll_acc += __shfl_xor_sync(0xffffffffu, nll_acc, o);
    if ((tid & 31) == 0) sm->red[tid >> 5] = nll_acc;
    __syncthreads();
    if (tid == 0) {
        float s = 0.f;
#pragma unroll
        for (int i = 0; i < 8; i++) s += sm->red[i];
        g_nllb[bid] = (double)s;
    }
}

__global__ void finalize_kernel(float* out, int nblocks) {
    double s = 0.0;
    for (int i = 0; i < nblocks; i++) s += g_nllb[i];
    out[0] = (float)s;
    g_bar = 0u;
}

extern "C" void kernel_launch(void* const* d_in, const int* in_sizes, int n_in,
                              void* d_out, int out_size) {
    const float* y      = (const float*)d_in[0];
    const float* dec_w1 = (const float*)d_in[1];
    const float* dec_b1 = (const float*)d_in[2];
    const float* dec_w2 = (const float*)d_in[3];
    const float* dec_b2 = (const float*)d_in[4];
    const float* mean_w = (const float*)d_in[5];
    const float* mean_b = (const float*)d_in[6];
    const float* std_w  = (const float*)d_in[7];
    const float* std_b  = (const float*)d_in[8];
    const float* wih0   = (const float*)d_in[9];
    const float* whh0   = (const float*)d_in[10];
    const float* bih0   = (const float*)d_in[11];
    const float* bhh0   = (const float*)d_in[12];
    const float* wih1   = (const float*)d_in[13];
    const float* whh1   = (const float*)d_in[14];
    const float* bih1   = (const float*)d_in[15];
    const float* bhh1   = (const float*)d_in[16];

    cudaFuncSetAttribute(rnn_mma, cudaFuncAttributeMaxDynamicSharedMemorySize,
                         (int)sizeof(SmemS));
    int dev = 0, nsm = 0, bpm = 0;
    cudaGetDevice(&dev);
    cudaDeviceGetAttribute(&nsm, cudaDevAttrMultiProcessorCount, dev);
    cudaOccupancyMaxActiveBlocksPerMultiprocessor(&bpm, rnn_mma, 256, sizeof(SmemS));
    if (bpm < 1) bpm = 1;
    if (bpm > 2) bpm = 2;
    int grid = nsm * bpm;
    if (grid > 2048) grid = 2048;

    rnn_mma<<<grid, 256, sizeof(SmemS)>>>(y, dec_w1, dec_b1, dec_w2, dec_b2,
                                          mean_w, mean_b, std_w, std_b,
                                          wih0, whh0, bih0, bhh0,
                                          wih1, whh1, bih1, bhh1);
    finalize_kernel<<<1, 1>>>((float*)d_out, grid);
}